// round 15
// baseline (speedup 1.0000x reference)
#include <cuda_runtime.h>
#include <cstdint>

// ===========================================================================
// RSNN forward (serial pipeline).
// Phase 1: inp = x @ w_in^T fp32 SIMT GEMM — R10 arithmetic (k-ascending
//   FFMA per output, bitwise stable) with (a) 4x8 warp microtile mapping and
//   (b) XOR bank-swizzled B smem -> conflict-free LDS (10 -> 4 cyc/k/warp).
// Phase 2: recurrent scan (R14 gather) with w_out readout staged in padded
//   dynamic smem (same values, same add order -> bitwise identical).
// ===========================================================================

#define T_STEPS 250
#define BATCH   256
#define IN_F    700
#define HID     1024
#define OUT_F   20
#define M_TOTAL (T_STEPS * BATCH)   // 64000

#define ALPHA_S 0.9048374180359595f
#define ALPHA_N 0.9753099120283326f

#define BM 128
#define BN 128
#define BK 16
#define NTILE 44

#define WPAD 21                               // w_outT row stride (gcd(21,32)=1)
#define SCAN_SMEM ((HID * WPAD + 2 * HID) * 4)  // 94208 B

// ---- scratch (device globals) ----
__device__ float g_inp[(size_t)M_TOTAL * HID];   // 262 MB
__device__ float g_wrecT[(size_t)HID * HID];     // 4 MB

// column swizzle for Bs: chunk c (16B) -> c ^ ((c>>3)&1)
__device__ __forceinline__ int swz(int n) {
    int c = n >> 2;
    c ^= (c >> 3) & 1;
    return (c << 2) | (n & 3);
}

// ---------------------------------------------------------------------------
// fp32 GEMM: R10 arithmetic, conflict-free LDS schedule.
// ---------------------------------------------------------------------------
__global__ void __launch_bounds__(256) gemm_in(const float* __restrict__ X,
                                               const float* __restrict__ W) {
    __shared__ float As[2][BK][BM];
    __shared__ float Bs[2][BK][BN];

    int tid = threadIdx.x;
    int wid = tid >> 5;
    int lane = tid & 31;
    // 4x8 warp microtile block: A loads 4 distinct rows, B loads 8 distinct
    int ty = (wid >> 1) * 4 + (lane >> 3);   // 0..15
    int tx = (wid & 1) * 8 + (lane & 7);     // 0..15

    int lr = tid >> 1;          // staging row 0..127
    int lk = (tid & 1) * 8;     // staging k offset 0 or 8
    int slr = swz(lr);          // swizzled B column for stores

    // swizzled float4 base indices for the two B chunks this thread reads
    int bc0 = ((tx * 2) ^ (((tx * 2) >> 3) & 1)) << 2;
    int bc1 = ((tx * 2 + 1) ^ (((tx * 2 + 1) >> 3) & 1)) << 2;

    size_t bm = (size_t)blockIdx.y * BM;
    size_t bn = (size_t)blockIdx.x * BN;

    float acc[8][8];
#pragma unroll
    for (int i = 0; i < 8; i++)
#pragma unroll
        for (int j = 0; j < 8; j++) acc[i][j] = 0.f;

    const float* Arow = X + (bm + lr) * IN_F;
    const float* Brow = W + (bn + lr) * IN_F;

    // prologue: tile 0 into stage 0
    {
        float4 a0 = *(const float4*)(Arow + lk);
        float4 a1 = *(const float4*)(Arow + lk + 4);
        float4 b0 = *(const float4*)(Brow + lk);
        float4 b1 = *(const float4*)(Brow + lk + 4);
        As[0][lk + 0][lr] = a0.x; As[0][lk + 1][lr] = a0.y;
        As[0][lk + 2][lr] = a0.z; As[0][lk + 3][lr] = a0.w;
        As[0][lk + 4][lr] = a1.x; As[0][lk + 5][lr] = a1.y;
        As[0][lk + 6][lr] = a1.z; As[0][lk + 7][lr] = a1.w;
        Bs[0][lk + 0][slr] = b0.x; Bs[0][lk + 1][slr] = b0.y;
        Bs[0][lk + 2][slr] = b0.z; Bs[0][lk + 3][slr] = b0.w;
        Bs[0][lk + 4][slr] = b1.x; Bs[0][lk + 5][slr] = b1.y;
        Bs[0][lk + 6][slr] = b1.z; Bs[0][lk + 7][slr] = b1.w;
    }

    for (int t = 0; t < NTILE; t++) {
        int st = t & 1;
        bool haveNext = (t + 1) < NTILE;
        float sa[8], sb[8];
        if (haveNext) {
            int k0 = (t + 1) * BK;
            if (t + 1 < NTILE - 1) {
                float4 a0 = *(const float4*)(Arow + k0 + lk);
                float4 a1 = *(const float4*)(Arow + k0 + lk + 4);
                float4 b0 = *(const float4*)(Brow + k0 + lk);
                float4 b1 = *(const float4*)(Brow + k0 + lk + 4);
                sa[0] = a0.x; sa[1] = a0.y; sa[2] = a0.z; sa[3] = a0.w;
                sa[4] = a1.x; sa[5] = a1.y; sa[6] = a1.z; sa[7] = a1.w;
                sb[0] = b0.x; sb[1] = b0.y; sb[2] = b0.z; sb[3] = b0.w;
                sb[4] = b1.x; sb[5] = b1.y; sb[6] = b1.z; sb[7] = b1.w;
            } else {
#pragma unroll
                for (int i = 0; i < 8; i++) {
                    int k = k0 + lk + i;
                    sa[i] = (k < IN_F) ? Arow[k] : 0.f;
                    sb[i] = (k < IN_F) ? Brow[k] : 0.f;
                }
            }
        }

        __syncthreads();

#pragma unroll
        for (int k = 0; k < BK; k++) {
            float4 a0 = *(const float4*)&As[st][k][ty * 8];
            float4 a1 = *(const float4*)&As[st][k][ty * 8 + 4];
            float4 b0 = *(const float4*)&Bs[st][k][bc0];
            float4 b1 = *(const float4*)&Bs[st][k][bc1];
            float a[8] = {a0.x, a0.y, a0.z, a0.w, a1.x, a1.y, a1.z, a1.w};
            float b[8] = {b0.x, b0.y, b0.z, b0.w, b1.x, b1.y, b1.z, b1.w};
#pragma unroll
            for (int i = 0; i < 8; i++)
#pragma unroll
                for (int j = 0; j < 8; j++) acc[i][j] += a[i] * b[j];
        }

        if (haveNext) {
            int ns = st ^ 1;
#pragma unroll
            for (int i = 0; i < 8; i++) {
                As[ns][lk + i][lr] = sa[i];
                Bs[ns][lk + i][slr] = sb[i];
            }
        }
    }

#pragma unroll
    for (int i = 0; i < 8; i++) {
        float* Crow = g_inp + (bm + ty * 8 + i) * HID + bn + tx * 8;
        *(float4*)Crow       = make_float4(acc[i][0], acc[i][1], acc[i][2], acc[i][3]);
        *(float4*)(Crow + 4) = make_float4(acc[i][4], acc[i][5], acc[i][6], acc[i][7]);
    }
}

// ---------------------------------------------------------------------------
__global__ void transpose_wrec(const float* __restrict__ w) {
    __shared__ float tile[32][33];
    int x0 = blockIdx.x * 32, y0 = blockIdx.y * 32;
    int tx = threadIdx.x, ty = threadIdx.y;
#pragma unroll
    for (int i = 0; i < 32; i += 8)
        tile[ty + i][tx] = w[(size_t)(y0 + ty + i) * HID + (x0 + tx)];
    __syncthreads();
#pragma unroll
    for (int i = 0; i < 32; i += 8)
        g_wrecT[(size_t)(x0 + ty + i) * HID + (y0 + tx)] = tile[tx][ty + i];
}

// ---------------------------------------------------------------------------
// recurrent scan (R14 gather; readout from padded smem w_outT)
// ---------------------------------------------------------------------------
__global__ void __launch_bounds__(256, 2) rsnn_kernel(
    const float* __restrict__ w_out,
    float* __restrict__ out_hist,
    float* __restrict__ spk_hist)
{
    extern __shared__ float dynsm[];
    float* w_outT = dynsm;                          // [HID][WPAD]
    int*   s_list = (int*)(dynsm + HID * WPAD);     // [2][HID]

    __shared__ int   s_cnt[2];
    __shared__ int   s_wsum[8];
    __shared__ float s_out[OUT_F];

    int b = blockIdx.x;
    int tid = threadIdx.x;          // owns h = 4*tid .. 4*tid+3
    int lane = tid & 31;
    int warp = tid >> 5;            // 0..7

    // stage w_out transposed into smem (exact copy -> same values)
    for (int i = tid; i < OUT_F * HID; i += 256) {
        int o = i >> 10;
        int h = i & (HID - 1);
        w_outT[h * WPAD + o] = w_out[i];
    }
    if (tid < 2) s_cnt[tid] = 0;
    if (tid < OUT_F) s_out[tid] = 0.f;

    float syn0 = 0.f, syn1 = 0.f, syn2 = 0.f, syn3 = 0.f;
    float mem0 = 0.f, mem1 = 0.f, mem2 = 0.f, mem3 = 0.f;

    const float* inp_b = g_inp + (size_t)b * HID + 4 * tid;
    float* spk_b = spk_hist + (size_t)b * T_STEPS * HID + 4 * tid;
    float* out_b = out_hist + (size_t)b * T_STEPS * OUT_F;
    const float* wrec_c = g_wrecT + 4 * tid;

    __syncthreads();

    for (int t = 0; t < T_STEPS; t++) {
        int p = t & 1, q = p ^ 1;

        float4 inpv = *(const float4*)(inp_b + (size_t)t * (BATCH * HID));

        // sparse gather: LDG.128 per spike, 8-wide unroll, ascending index
        int s = s_cnt[p];
        const int* lst = s_list + p * HID;
        float r0 = 0.f, r1 = 0.f, r2 = 0.f, r3 = 0.f;
        int i = 0;
        for (; i + 8 <= s; i += 8) {
            float4 v0 = *(const float4*)(wrec_c + (size_t)lst[i + 0] * HID);
            float4 v1 = *(const float4*)(wrec_c + (size_t)lst[i + 1] * HID);
            float4 v2 = *(const float4*)(wrec_c + (size_t)lst[i + 2] * HID);
            float4 v3 = *(const float4*)(wrec_c + (size_t)lst[i + 3] * HID);
            float4 v4 = *(const float4*)(wrec_c + (size_t)lst[i + 4] * HID);
            float4 v5 = *(const float4*)(wrec_c + (size_t)lst[i + 5] * HID);
            float4 v6 = *(const float4*)(wrec_c + (size_t)lst[i + 6] * HID);
            float4 v7 = *(const float4*)(wrec_c + (size_t)lst[i + 7] * HID);
            r0 += v0.x; r1 += v0.y; r2 += v0.z; r3 += v0.w;
            r0 += v1.x; r1 += v1.y; r2 += v1.z; r3 += v1.w;
            r0 += v2.x; r1 += v2.y; r2 += v2.z; r3 += v2.w;
            r0 += v3.x; r1 += v3.y; r2 += v3.z; r3 += v3.w;
            r0 += v4.x; r1 += v4.y; r2 += v4.z; r3 += v4.w;
            r0 += v5.x; r1 += v5.y; r2 += v5.z; r3 += v5.w;
            r0 += v6.x; r1 += v6.y; r2 += v6.z; r3 += v6.w;
            r0 += v7.x; r1 += v7.y; r2 += v7.z; r3 += v7.w;
        }
        for (; i < s; i++) {
            float4 v = *(const float4*)(wrec_c + (size_t)lst[i] * HID);
            r0 += v.x; r1 += v.y; r2 += v.z; r3 += v.w;
        }

        float sv0 = (syn0 + inpv.x + r0) * ALPHA_S;
        float sv1 = (syn1 + inpv.y + r1) * ALPHA_S;
        float sv2 = (syn2 + inpv.z + r2) * ALPHA_S;
        float sv3 = (syn3 + inpv.w + r3) * ALPHA_S;
        syn0 = sv0; syn1 = sv1; syn2 = sv2; syn3 = sv3;
        bool z0 = mem0 > 1.0f, z1 = mem1 > 1.0f, z2 = mem2 > 1.0f, z3 = mem3 > 1.0f;
        mem0 = (z0 ? sv0 : (mem0 + sv0)) * ALPHA_N;
        mem1 = (z1 ? sv1 : (mem1 + sv1)) * ALPHA_N;
        mem2 = (z2 ? sv2 : (mem2 + sv2)) * ALPHA_N;
        mem3 = (z3 ? sv3 : (mem3 + sv3)) * ALPHA_N;

        *(float4*)(spk_b + (size_t)t * HID) = make_float4(
            z0 ? 1.f : 0.f, z1 ? 1.f : 0.f, z2 ? 1.f : 0.f, z3 ? 1.f : 0.f);

        // deterministic compaction, list ascending h
        int nz = (int)z0 + (int)z1 + (int)z2 + (int)z3;
        int v = nz;
#pragma unroll
        for (int off = 1; off < 32; off <<= 1) {
            int n = __shfl_up_sync(0xffffffffu, v, off);
            if (lane >= off) v += n;
        }
        if (lane == 31) s_wsum[warp] = v;
        __syncthreads();
        if (tid == 0) {
            int run = 0;
#pragma unroll
            for (int w = 0; w < 8; w++) { run += s_wsum[w]; s_wsum[w] = run; }
            s_cnt[q] = run;
        }
        __syncthreads();
        {
            int base = (warp ? s_wsum[warp - 1] : 0) + (v - nz);
            int h0 = 4 * tid;
            int* dst = s_list + q * HID;
            if (z0) dst[base++] = h0;
            if (z1) dst[base++] = h0 + 1;
            if (z2) dst[base++] = h0 + 2;
            if (z3) dst[base++] = h0 + 3;
        }
        __syncthreads();

        // readout from smem w_outT (same values, same add order as before)
        int cs = s_cnt[q];
        const int* lq = s_list + q * HID;
        for (int o = warp; o < OUT_F; o += 8) {
            float sum = 0.f;
            for (int k = lane; k < cs; k += 32)
                sum += w_outT[lq[k] * WPAD + o];
#pragma unroll
            for (int off = 16; off; off >>= 1)
                sum += __shfl_down_sync(0xffffffffu, sum, off);
            if (lane == 0) {
                float ov = (s_out[o] + sum) * ALPHA_S;
                s_out[o] = ov;
                out_b[(size_t)t * OUT_F + o] = ov;
            }
        }
        __syncthreads();
    }
}

// ---------------------------------------------------------------------------
extern "C" void kernel_launch(void* const* d_in, const int* in_sizes, int n_in,
                              void* d_out, int out_size) {
    const float* x     = (const float*)d_in[0];
    const float* w_in  = (const float*)d_in[1];
    const float* w_rec = (const float*)d_in[2];
    const float* w_out = (const float*)d_in[3];

    float* out_hist = (float*)d_out;
    float* spk_hist = out_hist + (size_t)BATCH * T_STEPS * OUT_F;

    static int smem_set = 0;
    if (!smem_set) {
        cudaFuncSetAttribute(rsnn_kernel,
                             cudaFuncAttributeMaxDynamicSharedMemorySize,
                             SCAN_SMEM);
        smem_set = 1;
    }

    // GEMM first (profiler capture slot), transpose second, scan last.
    gemm_in<<<dim3(HID / BN, M_TOTAL / BM), 256>>>(x, w_in);
    transpose_wrec<<<dim3(HID / 32, HID / 32), dim3(32, 8)>>>(w_rec);
    rsnn_kernel<<<BATCH, 256, SCAN_SMEM>>>(w_out, out_hist, spk_hist);
}

// round 17
// speedup vs baseline: 1.0644x; 1.0644x over previous
#include <cuda_runtime.h>
#include <cstdint>

// ===========================================================================
// RSNN forward (serial pipeline).
// Phase 1: inp = x @ w_in^T fp32 SIMT GEMM — single-buffered smem (R1
//   schedule; R8 proved double-buffering is worth ~0 here) + R15's
//   conflict-free LDS (4x8 warp microtile, XOR-swizzled Bs). No staging
//   registers -> ~105 regs -> 2 CTAs/SM naturally (no launch_bounds cap,
//   which is the suspect in R16's illegal-access).
// Phase 2: recurrent scan — R14 verbatim (the 7019us build's scan).
// All per-output accumulation orders unchanged -> bitwise-identical output.
// ===========================================================================

#define T_STEPS 250
#define BATCH   256
#define IN_F    700
#define HID     1024
#define OUT_F   20
#define M_TOTAL (T_STEPS * BATCH)   // 64000

#define ALPHA_S 0.9048374180359595f
#define ALPHA_N 0.9753099120283326f

#define BM 128
#define BN 128
#define BK 16
#define NTILE 44

// ---- scratch (device globals) ----
__device__ float g_inp[(size_t)M_TOTAL * HID];   // 262 MB
__device__ float g_wrecT[(size_t)HID * HID];     // 4 MB

// column swizzle for Bs: chunk c (16B) -> c ^ ((c>>3)&1)
__device__ __forceinline__ int swz(int n) {
    int c = n >> 2;
    c ^= (c >> 3) & 1;
    return (c << 2) | (n & 3);
}

// ---------------------------------------------------------------------------
// fp32 GEMM: R10 arithmetic, single-buffer smem, conflict-free LDS.
// ---------------------------------------------------------------------------
__global__ void __launch_bounds__(256) gemm_in(const float* __restrict__ X,
                                               const float* __restrict__ W) {
    __shared__ float As[BK][BM];
    __shared__ float Bs[BK][BN];

    int tid = threadIdx.x;
    int wid = tid >> 5;
    int lane = tid & 31;
    // 4x8 warp microtile: A reads 4 distinct 16B rows, B reads 8 distinct
    int ty = (wid >> 1) * 4 + (lane >> 3);   // 0..15
    int tx = (wid & 1) * 8 + (lane & 7);     // 0..15

    int lr = tid >> 1;          // staging row 0..127
    int lk = (tid & 1) * 8;     // staging k offset 0 or 8
    int slr = swz(lr);          // swizzled B column for stores

    // swizzled float4 base indices for the two B chunks this thread reads
    int bc0 = ((tx * 2) ^ (((tx * 2) >> 3) & 1)) << 2;
    int bc1 = ((tx * 2 + 1) ^ (((tx * 2 + 1) >> 3) & 1)) << 2;

    size_t bm = (size_t)blockIdx.y * BM;
    size_t bn = (size_t)blockIdx.x * BN;

    float acc[8][8];
#pragma unroll
    for (int i = 0; i < 8; i++)
#pragma unroll
        for (int j = 0; j < 8; j++) acc[i][j] = 0.f;

    const float* Arow = X + (bm + lr) * IN_F;
    const float* Brow = W + (bn + lr) * IN_F;

    for (int t = 0; t < NTILE; t++) {
        int k0 = t * BK;
        __syncthreads();    // previous compute done before overwrite
        if (t < NTILE - 1) {
            float4 a0 = *(const float4*)(Arow + k0 + lk);
            float4 a1 = *(const float4*)(Arow + k0 + lk + 4);
            float4 b0 = *(const float4*)(Brow + k0 + lk);
            float4 b1 = *(const float4*)(Brow + k0 + lk + 4);
            As[lk + 0][lr] = a0.x; As[lk + 1][lr] = a0.y;
            As[lk + 2][lr] = a0.z; As[lk + 3][lr] = a0.w;
            As[lk + 4][lr] = a1.x; As[lk + 5][lr] = a1.y;
            As[lk + 6][lr] = a1.z; As[lk + 7][lr] = a1.w;
            Bs[lk + 0][slr] = b0.x; Bs[lk + 1][slr] = b0.y;
            Bs[lk + 2][slr] = b0.z; Bs[lk + 3][slr] = b0.w;
            Bs[lk + 4][slr] = b1.x; Bs[lk + 5][slr] = b1.y;
            Bs[lk + 6][slr] = b1.z; Bs[lk + 7][slr] = b1.w;
        } else {
#pragma unroll
            for (int i = 0; i < 8; i++) {
                int k = k0 + lk + i;
                As[lk + i][lr]  = (k < IN_F) ? Arow[k] : 0.f;
                Bs[lk + i][slr] = (k < IN_F) ? Brow[k] : 0.f;
            }
        }
        __syncthreads();

#pragma unroll
        for (int k = 0; k < BK; k++) {
            float4 a0 = *(const float4*)&As[k][ty * 8];
            float4 a1 = *(const float4*)&As[k][ty * 8 + 4];
            float4 b0 = *(const float4*)&Bs[k][bc0];
            float4 b1 = *(const float4*)&Bs[k][bc1];
            float a[8] = {a0.x, a0.y, a0.z, a0.w, a1.x, a1.y, a1.z, a1.w};
            float b[8] = {b0.x, b0.y, b0.z, b0.w, b1.x, b1.y, b1.z, b1.w};
#pragma unroll
            for (int i = 0; i < 8; i++)
#pragma unroll
                for (int j = 0; j < 8; j++) acc[i][j] += a[i] * b[j];
        }
    }

#pragma unroll
    for (int i = 0; i < 8; i++) {
        float* Crow = g_inp + (bm + ty * 8 + i) * HID + bn + tx * 8;
        *(float4*)Crow       = make_float4(acc[i][0], acc[i][1], acc[i][2], acc[i][3]);
        *(float4*)(Crow + 4) = make_float4(acc[i][4], acc[i][5], acc[i][6], acc[i][7]);
    }
}

// ---------------------------------------------------------------------------
__global__ void transpose_wrec(const float* __restrict__ w) {
    __shared__ float tile[32][33];
    int x0 = blockIdx.x * 32, y0 = blockIdx.y * 32;
    int tx = threadIdx.x, ty = threadIdx.y;
#pragma unroll
    for (int i = 0; i < 32; i += 8)
        tile[ty + i][tx] = w[(size_t)(y0 + ty + i) * HID + (x0 + tx)];
    __syncthreads();
#pragma unroll
    for (int i = 0; i < 32; i += 8)
        g_wrecT[(size_t)(x0 + ty + i) * HID + (y0 + tx)] = tile[tx][ty + i];
}

// ---------------------------------------------------------------------------
// recurrent scan (R14 verbatim)
// ---------------------------------------------------------------------------
__global__ void __launch_bounds__(256, 4) rsnn_kernel(
    const float* __restrict__ w_out,
    float* __restrict__ out_hist,
    float* __restrict__ spk_hist)
{
    int b = blockIdx.x;
    int tid = threadIdx.x;          // owns h = 4*tid .. 4*tid+3
    int lane = tid & 31;
    int warp = tid >> 5;            // 0..7

    __shared__ int   s_list[2][HID];
    __shared__ int   s_cnt[2];
    __shared__ int   s_wsum[8];
    __shared__ float s_out[OUT_F];

    if (tid < 2) s_cnt[tid] = 0;
    if (tid < OUT_F) s_out[tid] = 0.f;

    float syn0 = 0.f, syn1 = 0.f, syn2 = 0.f, syn3 = 0.f;
    float mem0 = 0.f, mem1 = 0.f, mem2 = 0.f, mem3 = 0.f;

    const float* inp_b = g_inp + (size_t)b * HID + 4 * tid;
    float* spk_b = spk_hist + (size_t)b * T_STEPS * HID + 4 * tid;
    float* out_b = out_hist + (size_t)b * T_STEPS * OUT_F;
    const float* wrec_c = g_wrecT + 4 * tid;

    __syncthreads();

    for (int t = 0; t < T_STEPS; t++) {
        int p = t & 1, q = p ^ 1;

        float4 inpv = *(const float4*)(inp_b + (size_t)t * (BATCH * HID));

        int s = s_cnt[p];
        const int* lst = s_list[p];
        float r0 = 0.f, r1 = 0.f, r2 = 0.f, r3 = 0.f;
        int i = 0;
        for (; i + 8 <= s; i += 8) {
            float4 v0 = *(const float4*)(wrec_c + (size_t)lst[i + 0] * HID);
            float4 v1 = *(const float4*)(wrec_c + (size_t)lst[i + 1] * HID);
            float4 v2 = *(const float4*)(wrec_c + (size_t)lst[i + 2] * HID);
            float4 v3 = *(const float4*)(wrec_c + (size_t)lst[i + 3] * HID);
            float4 v4 = *(const float4*)(wrec_c + (size_t)lst[i + 4] * HID);
            float4 v5 = *(const float4*)(wrec_c + (size_t)lst[i + 5] * HID);
            float4 v6 = *(const float4*)(wrec_c + (size_t)lst[i + 6] * HID);
            float4 v7 = *(const float4*)(wrec_c + (size_t)lst[i + 7] * HID);
            r0 += v0.x; r1 += v0.y; r2 += v0.z; r3 += v0.w;
            r0 += v1.x; r1 += v1.y; r2 += v1.z; r3 += v1.w;
            r0 += v2.x; r1 += v2.y; r2 += v2.z; r3 += v2.w;
            r0 += v3.x; r1 += v3.y; r2 += v3.z; r3 += v3.w;
            r0 += v4.x; r1 += v4.y; r2 += v4.z; r3 += v4.w;
            r0 += v5.x; r1 += v5.y; r2 += v5.z; r3 += v5.w;
            r0 += v6.x; r1 += v6.y; r2 += v6.z; r3 += v6.w;
            r0 += v7.x; r1 += v7.y; r2 += v7.z; r3 += v7.w;
        }
        for (; i < s; i++) {
            float4 v = *(const float4*)(wrec_c + (size_t)lst[i] * HID);
            r0 += v.x; r1 += v.y; r2 += v.z; r3 += v.w;
        }

        float sv0 = (syn0 + inpv.x + r0) * ALPHA_S;
        float sv1 = (syn1 + inpv.y + r1) * ALPHA_S;
        float sv2 = (syn2 + inpv.z + r2) * ALPHA_S;
        float sv3 = (syn3 + inpv.w + r3) * ALPHA_S;
        syn0 = sv0; syn1 = sv1; syn2 = sv2; syn3 = sv3;
        bool z0 = mem0 > 1.0f, z1 = mem1 > 1.0f, z2 = mem2 > 1.0f, z3 = mem3 > 1.0f;
        mem0 = (z0 ? sv0 : (mem0 + sv0)) * ALPHA_N;
        mem1 = (z1 ? sv1 : (mem1 + sv1)) * ALPHA_N;
        mem2 = (z2 ? sv2 : (mem2 + sv2)) * ALPHA_N;
        mem3 = (z3 ? sv3 : (mem3 + sv3)) * ALPHA_N;

        *(float4*)(spk_b + (size_t)t * HID) = make_float4(
            z0 ? 1.f : 0.f, z1 ? 1.f : 0.f, z2 ? 1.f : 0.f, z3 ? 1.f : 0.f);

        int nz = (int)z0 + (int)z1 + (int)z2 + (int)z3;
        int v = nz;
#pragma unroll
        for (int off = 1; off < 32; off <<= 1) {
            int n = __shfl_up_sync(0xffffffffu, v, off);
            if (lane >= off) v += n;
        }
        if (lane == 31) s_wsum[warp] = v;
        __syncthreads();
        if (tid == 0) {
            int run = 0;
#pragma unroll
            for (int w = 0; w < 8; w++) { run += s_wsum[w]; s_wsum[w] = run; }
            s_cnt[q] = run;
        }
        __syncthreads();
        {
            int base = (warp ? s_wsum[warp - 1] : 0) + (v - nz);
            int h0 = 4 * tid;
            int* dst = s_list[q];
            if (z0) dst[base++] = h0;
            if (z1) dst[base++] = h0 + 1;
            if (z2) dst[base++] = h0 + 2;
            if (z3) dst[base++] = h0 + 3;
        }
        __syncthreads();

        int cs = s_cnt[q];
        const int* lq = s_list[q];
        for (int o = warp; o < OUT_F; o += 8) {
            const float* wrow = w_out + (size_t)o * HID;
            float sum = 0.f;
            for (int k = lane; k < cs; k += 32)
                sum += wrow[lq[k]];
#pragma unroll
            for (int off = 16; off; off >>= 1)
                sum += __shfl_down_sync(0xffffffffu, sum, off);
            if (lane == 0) {
                float ov = (s_out[o] + sum) * ALPHA_S;
                s_out[o] = ov;
                out_b[(size_t)t * OUT_F + o] = ov;
            }
        }
        __syncthreads();
    }
}

// ---------------------------------------------------------------------------
extern "C" void kernel_launch(void* const* d_in, const int* in_sizes, int n_in,
                              void* d_out, int out_size) {
    const float* x     = (const float*)d_in[0];
    const float* w_in  = (const float*)d_in[1];
    const float* w_rec = (const float*)d_in[2];
    const float* w_out = (const float*)d_in[3];

    float* out_hist = (float*)d_out;
    float* spk_hist = out_hist + (size_t)BATCH * T_STEPS * OUT_F;

    // GEMM first (profiler capture slot), transpose second, scan last.
    gemm_in<<<dim3(HID / BN, M_TOTAL / BM), 256>>>(x, w_in);
    transpose_wrec<<<dim3(HID / 32, HID / 32), dim3(32, 8)>>>(w_rec);
    rsnn_kernel<<<BATCH, 256>>>(w_out, out_hist, spk_hist);
}